// round 15
// baseline (speedup 1.0000x reference)
#include <cuda_runtime.h>
#include <cuda_fp16.h>
#include <math.h>
#include <stdint.h>

#define BB 64
#define TT 256
#define DD 1024
#define HH 8
#define GH 256
#define G3 768
#define MROWS (BB*TT)   // 16384

// ---------------- scratch (device globals; allocation forbidden) -----------
__device__ __align__(16) __half g_Ah [MROWS*DD];   // fp16 A mirror (seg_h / X_h)
__device__ __align__(16) __half g_AOh[MROWS*DD];   // fp16 attention output
__device__ __align__(16) float  g_Xf [MROWS*DD];   // fp32 X after layer0
__device__ __align__(16) __half g_QKVh[MROWS*3072];// fused QKV output (fp16)
__device__ __align__(16) float  g_G  [MROWS*1536]; // fused GRU gx (fwd|bwd), fp32
__device__ __align__(16) __half g_Wh [9961472];    // fp16 concat weights
__device__ __align__(16) float  g_bias[9728];      // concat biases (fp32)
__device__ __align__(16) __half g_Hh [2*2*BB*GH];  // fp16 h exchange [dir][parity][b][GH]
__device__ __align__(128) unsigned g_bar2[64];     // [0]: fwd counter, [32]: bwd counter

// Weight region offsets (elements)
#define W_QKV0 0
#define W_O0   3145728
#define W_QKV1 4194304
#define W_O1   7340032
#define W_GRU  8388608
// Bias offsets
#define B_QKV0 0
#define B_O0   3072
#define B_QKV1 4096
#define B_O1   7168
#define B_GRU  8192

// ---------------------------------------------------------------------------
__device__ __forceinline__ uint32_t smem_u32(const void* p) {
    uint32_t a;
    asm("{ .reg .u64 t; cvta.to.shared.u64 t, %1; cvt.u32.u64 %0, t; }" : "=r"(a) : "l"(p));
    return a;
}
__device__ __forceinline__ void cp_async16(uint32_t dst_smem, const void* src) {
    asm volatile("cp.async.cg.shared.global [%0], [%1], 16;" :: "r"(dst_smem), "l"(src));
}
#define CP_COMMIT() asm volatile("cp.async.commit_group;" ::: "memory")
#define CP_WAIT1()  asm volatile("cp.async.wait_group 1;" ::: "memory")
#define CP_WAIT0()  asm volatile("cp.async.wait_group 0;" ::: "memory")

#define LDSM4(r0, r1, r2, r3, addr) \
    asm volatile("ldmatrix.sync.aligned.m8n8.x4.shared.b16 {%0,%1,%2,%3}, [%4];" \
        : "=r"(r0), "=r"(r1), "=r"(r2), "=r"(r3) : "r"(addr))

__device__ __forceinline__ void mma_f16(float* d, const uint32_t* a, const uint32_t* b) {
    asm volatile(
        "mma.sync.aligned.m16n8k16.row.col.f32.f16.f16.f32 "
        "{%0,%1,%2,%3}, {%4,%5,%6,%7}, {%8,%9}, {%0,%1,%2,%3};"
        : "+f"(d[0]), "+f"(d[1]), "+f"(d[2]), "+f"(d[3])
        : "r"(a[0]), "r"(a[1]), "r"(a[2]), "r"(a[3]), "r"(b[0]), "r"(b[1]));
}

__device__ __forceinline__ float4 ld_h4(const __half* p) {
    const uint2 u = *(const uint2*)p;
    const __half2* h = (const __half2*)&u;
    const float2 f01 = __half22float2(h[0]);
    const float2 f23 = __half22float2(h[1]);
    return make_float4(f01.x, f01.y, f23.x, f23.y);
}

// ---------------------------------------------------------------------------
// prep: all 10 weight matrices -> fp16 concat (dst is contiguous flat index)
// ---------------------------------------------------------------------------
__global__ void prep_weights(const float* __restrict__ Wq, const float* __restrict__ Wk,
                             const float* __restrict__ Wv, const float* __restrict__ Wo,
                             const float* __restrict__ Wihf, const float* __restrict__ Wihb) {
    const int MW4 = 262144;   // 1M floats / 4
    const int GW4 = 196608;   // 768K floats / 4
    const long total = 8L * MW4 + 2L * GW4;   // 2490368 float4s
    const float* srcs[10] = {Wq, Wk, Wv, Wo,
                             Wq + 1048576, Wk + 1048576, Wv + 1048576, Wo + 1048576,
                             Wihf, Wihb};
    const long stride = (long)gridDim.x * blockDim.x;
    for (long idx = (long)blockIdx.x * blockDim.x + threadIdx.x; idx < total; idx += stride) {
        int r; long off;
        if (idx < 8L * MW4) { r = (int)(idx >> 18); off = idx & (MW4 - 1); }
        else {
            long k = idx - 8L * MW4;
            r = 8 + (int)(k >= GW4);
            off = k - (long)(r - 8) * GW4;
        }
        const float4 v = ((const float4*)srcs[r])[off];
        __half2 h01 = __floats2half2_rn(v.x, v.y);
        __half2 h23 = __floats2half2_rn(v.z, v.w);
        uint2 u;
        u.x = *(uint32_t*)&h01;
        u.y = *(uint32_t*)&h23;
        ((uint2*)g_Wh)[idx] = u;
    }
}

// ---------------------------------------------------------------------------
// prep: concat biases + zero h parity-0 + zero barrier counters
// ---------------------------------------------------------------------------
__global__ void prep_small(const float* __restrict__ bq, const float* __restrict__ bk,
                           const float* __restrict__ bv, const float* __restrict__ bo,
                           const float* __restrict__ bihf, const float* __restrict__ bihb) {
    const float* bsrc[8] = {bq, bk, bv, bo, bq + 1024, bk + 1024, bv + 1024, bo + 1024};
    const int stride = gridDim.x * blockDim.x;
    for (int idx = blockIdx.x * blockDim.x + threadIdx.x; idx < 16384; idx += stride) {
        if (idx < 9728) {
            float val;
            if (idx < 8192)       val = bsrc[idx >> 10][idx & 1023];
            else if (idx < 8960)  val = bihf[idx - 8192];
            else                  val = bihb[idx - 8960];
            g_bias[idx] = val;
        }
        if (idx < BB*GH/2) {
            ((uint32_t*)g_Hh)[idx] = 0u;                 // dir0 parity0
            ((uint32_t*)(g_Hh + 2*BB*GH))[idx] = 0u;     // dir1 parity0
        }
        if (idx < 64) g_bar2[idx] = 0u;
    }
}

__global__ void to_half(const float* __restrict__ src, __half* __restrict__ dst, int n4) {
    int i = blockIdx.x * blockDim.x + threadIdx.x;
    int stride = gridDim.x * blockDim.x;
    for (int k = i; k < n4; k += stride) {
        float4 v = ((const float4*)src)[k];
        __half2 h01 = __floats2half2_rn(v.x, v.y);
        __half2 h23 = __floats2half2_rn(v.z, v.w);
        uint2 u;
        u.x = *(uint32_t*)&h01;
        u.y = *(uint32_t*)&h23;
        ((uint2*)dst)[k] = u;
    }
}

// ---------------------------------------------------------------------------
// fp16 mma GEMM, warp tile 64x64: C = A[M,1024] @ W[Nc,1024]^T + bias
// BM=128, BN=256, BK=32, 8 warps (2x4), 3-stage cp.async, 1 CTA/SM.
// LDSM traffic per unit output cut 1.55x vs 64x32 warp tile; 32 independent
// MMAs per ks give the tensor pipe a dependency-free stream.
// ---------------------------------------------------------------------------
#define SKH 20                            // b32 units per smem row (80B)
#define A_U32 (128*SKH)                   // 2560
#define STAGE_U32 (384*SKH)               // A(128 rows)+B(256 rows) = 7680
#define GEMM_SMEM (3 * STAGE_U32 * 4)     // 92160 bytes

__global__ __launch_bounds__(256, 1)
void mma_gemm(const __half* __restrict__ A, const __half* __restrict__ Wp,
              const float* __restrict__ bias, const float* __restrict__ res,
              float* __restrict__ Cf, __half* __restrict__ Ch, int Nc) {
    extern __shared__ uint32_t smu[];
    const uint32_t sbase = smem_u32(smu);
    const int tid  = threadIdx.x;
    const int wid  = tid >> 5;
    const int lane = tid & 31;
    const int warp_m = wid & 1;        // 0..1 (64-row half)
    const int warp_n = wid >> 1;       // 0..3 (64-col quarter)
    const int gid = lane >> 2;
    const int tig = lane & 3;
    const int bm = blockIdx.y * 128;
    const int bn = blockIdx.x * 256;

    // cp.async: A 512 chunks (2/thread), B 1024 chunks (4/thread)
    const int ldrA = tid >> 1;         // 0..127
    const int ldcA = (tid & 1) << 1;   // 0 or 2

    auto load_stage = [&](int kt, int p) {
        const uint32_t sA = sbase + p * STAGE_U32 * 4;
        const uint32_t sB = sA + A_U32 * 4;
        const __half* ga = A  + (long)(bm + ldrA) * DD + kt * 32;
        const __half* gb = Wp + (long)(bn + tid) * DD + kt * 32;
        #pragma unroll
        for (int c = 0; c < 2; c++) {
            const int ch = ldcA + c;
            cp_async16(sA + (ldrA * SKH + ch * 4) * 4, ga + ch * 8);
        }
        #pragma unroll
        for (int c = 0; c < 4; c++) {
            cp_async16(sB + (tid * SKH + c * 4) * 4, gb + c * 8);
        }
    };

    float acc[4][8][4];
    #pragma unroll
    for (int mt = 0; mt < 4; mt++)
        #pragma unroll
        for (int nt = 0; nt < 8; nt++)
            #pragma unroll
            for (int q = 0; q < 4; q++) acc[mt][nt][q] = 0.0f;

    const uint32_t a_loff = ((lane & 15) * SKH + (lane >> 4) * 4) * 4;
    const uint32_t b_loff = (((lane & 7) + (lane >> 4) * 8) * SKH + ((lane >> 3) & 1) * 4) * 4;

    const int NK = DD / 32;   // 32
    load_stage(0, 0); CP_COMMIT();
    load_stage(1, 1); CP_COMMIT();

    for (int kt = 0; kt < NK; kt++) {
        CP_WAIT1();
        __syncthreads();
        if (kt + 2 < NK) load_stage(kt + 2, (kt + 2) % 3);
        CP_COMMIT();

        const uint32_t sAb = sbase + (kt % 3) * STAGE_U32 * 4;
        const uint32_t sBb = sAb + A_U32 * 4;
        const int mb = warp_m * 64;
        const int nb = warp_n * 64;
        #pragma unroll
        for (int ks = 0; ks < 2; ks++) {
            uint32_t afr[4][4], bfr[8][2];
            #pragma unroll
            for (int mt = 0; mt < 4; mt++) {
                const uint32_t ad = sAb + a_loff + ((mb + mt * 16) * SKH + ks * 8) * 4;
                LDSM4(afr[mt][0], afr[mt][1], afr[mt][2], afr[mt][3], ad);
            }
            #pragma unroll
            for (int np = 0; np < 4; np++) {
                const uint32_t bd = sBb + b_loff + ((nb + np * 16) * SKH + ks * 8) * 4;
                LDSM4(bfr[2*np][0], bfr[2*np][1], bfr[2*np+1][0], bfr[2*np+1][1], bd);
            }
            #pragma unroll
            for (int mt = 0; mt < 4; mt++)
                #pragma unroll
                for (int nt = 0; nt < 8; nt++)
                    mma_f16(acc[mt][nt], afr[mt], bfr[nt]);
        }
        // buffer reuse ordered by the next iteration's post-wait barrier.
    }

    // epilogue
    #pragma unroll
    for (int mt = 0; mt < 4; mt++) {
        #pragma unroll
        for (int nt = 0; nt < 8; nt++) {
            const long row0 = bm + warp_m * 64 + mt * 16 + gid;
            const int  colg = bn + warp_n * 64 + nt * 8 + 2 * tig;
            #pragma unroll
            for (int hf = 0; hf < 2; hf++) {
                const long row = row0 + hf * 8;
                float2 v;
                v.x = acc[mt][nt][hf * 2 + 0];
                v.y = acc[mt][nt][hf * 2 + 1];
                const float2 bv = *(const float2*)(bias + colg);
                v.x += bv.x; v.y += bv.y;
                if (res) {
                    const float2 rv = *(const float2*)(res + row * Nc + colg);
                    v.x += rv.x; v.y += rv.y;
                }
                if (Cf) *(float2*)(Cf + row * Nc + colg) = v;
                if (Ch) {
                    __half2 hv = __floats2half2_rn(v.x, v.y);
                    *(__half2*)(Ch + row * Nc + colg) = hv;
                }
            }
        }
    }
}

// ---------------------------------------------------------------------------
// Tiled banded attention: block = (b, h, s-tile of 64). K/V band rows staged
// in smem via cp.async (<=70 rows x 256B each). 8 warps, 8 s per warp.
// ---------------------------------------------------------------------------
__global__ __launch_bounds__(256)
void attn_kernel(const __half* __restrict__ QKV, __half* __restrict__ Oh) {
    __shared__ __half Ks[70][128];
    __shared__ __half Vs[70][128];

    const int tid = threadIdx.x;
    const int st = blockIdx.x & 3;
    const int h  = (blockIdx.x >> 2) & 7;
    const int b  = blockIdx.x >> 5;
    const int s0 = st * 64;
    const int tlo = max(s0 - 3, 0);
    const int thi = min(s0 + 66, TT - 1);
    const int nrow = thi - tlo + 1;   // <= 70

    const long base = (long)(b * TT + tlo) * 3072 + h * 128;
    for (int idx = tid; idx < nrow * 16; idx += 256) {
        const int r = idx >> 4;
        const int c = idx & 15;
        cp_async16(smem_u32(&Ks[r][c * 8]), QKV + base + (long)r * 3072 + 1024 + c * 8);
        cp_async16(smem_u32(&Vs[r][c * 8]), QKV + base + (long)r * 3072 + 2048 + c * 8);
    }
    CP_COMMIT();
    CP_WAIT0();
    __syncthreads();

    const int wrp  = tid >> 5;
    const int lane = tid & 31;

    for (int i = 0; i < 8; i++) {
        const int s = s0 + wrp * 8 + i;
        const float4 q4 = ld_h4(QKV + (long)(b * TT + s) * 3072 + h * 128 + lane * 4);

        float sc[7];
        float m = -1e30f;
        #pragma unroll
        for (int j = 0; j < 7; j++) {
            const int t = s - 3 + j;
            const bool vld = (t >= 0) && (t < TT);
            const int ti = (vld ? t : (t < 0 ? 0 : TT - 1)) - tlo;
            const float4 k4 = ld_h4(&Ks[ti][lane * 4]);
            float p = q4.x*k4.x + q4.y*k4.y + q4.z*k4.z + q4.w*k4.w;
            p += __shfl_xor_sync(0xffffffffu, p, 16);
            p += __shfl_xor_sync(0xffffffffu, p, 8);
            p += __shfl_xor_sync(0xffffffffu, p, 4);
            p += __shfl_xor_sync(0xffffffffu, p, 2);
            p += __shfl_xor_sync(0xffffffffu, p, 1);
            p = vld ? (p * 0.088388347648318447f) : -1e30f;
            sc[j] = p;
            m = fmaxf(m, p);
        }
        float sum = 0.0f;
        #pragma unroll
        for (int j = 0; j < 7; j++) {
            const float e = __expf(sc[j] - m);
            sc[j] = e;
            sum += e;
        }
        const float inv = 1.0f / sum;
        float4 o = make_float4(0.f, 0.f, 0.f, 0.f);
        #pragma unroll
        for (int j = 0; j < 7; j++) {
            const int t = s - 3 + j;
            const int ti = ((t >= 0) ? ((t < TT) ? t : TT - 1) : 0) - tlo;
            const float w = sc[j] * inv;
            const float4 v4 = ld_h4(&Vs[ti][lane * 4]);
            o.x += w * v4.x; o.y += w * v4.y; o.z += w * v4.z; o.w += w * v4.w;
        }
        __half2 h01 = __floats2half2_rn(o.x, o.y);
        __half2 h23 = __floats2half2_rn(o.z, o.w);
        uint2 u;
        u.x = *(uint32_t*)&h01;
        u.y = *(uint32_t*)&h23;
        *(uint2*)(Oh + (long)(b * TT + s) * 1024 + h * 128 + lane * 4) = u;
    }
}

// ---------------------------------------------------------------------------
// BiGRU recurrence on tensor cores. 64 blocks x 512 thr (32 blocks/dir,
// 8 hidden units each). W_hh as persistent register b-fragments; h exchanged
// fp16 via L2; fp32 h carry thread-local. Per-DIRECTION monotonic-counter
// grid barrier (32 arrivals each; release-red + single acquire poller).
// ---------------------------------------------------------------------------
#define SKW 132   // u32 per smem row (256 halves + pad; 528B, 16B-mult)
#define GRU_SMEM ((32*SKW + 64*SKW) * 4 + 64*36*4)   // 59904 B

__device__ __forceinline__ float sigmoidf_(float x) { return 1.0f / (1.0f + expf(-x)); }

__global__ __launch_bounds__(512, 1)
void gru_kernel(const float* __restrict__ G,
                const float* __restrict__ Whhf, const float* __restrict__ Whhb,
                const float* __restrict__ bhhf, const float* __restrict__ bhhb,
                const int* __restrict__ seglen, float* __restrict__ out) {
    extern __shared__ uint32_t dsm[];
    uint32_t* sWu = dsm;                 // [32][SKW]
    uint32_t* sHu = dsm + 32 * SKW;      // [64][SKW]
    float*    sD  = (float*)(dsm + 96 * SKW);  // [64][36]

    const int tid = threadIdx.x;
    const int dir = blockIdx.x >> 5;
    const int jb  = (blockIdx.x & 31) * 8;
    const float* W  = dir ? Whhb : Whhf;
    const float* bh = dir ? bhhb : bhhf;
    unsigned* bar = g_bar2 + dir * 32;   // per-direction counter (128B apart)

    const int lane = tid & 31;
    const int wrp  = tid >> 5;            // 0..15
    const int mt   = wrp & 3;
    const int nt   = wrp >> 2;            // 0..3
    const int gid  = lane >> 2;
    const int tig  = lane & 3;

    const int b  = tid >> 3;              // 0..63
    const int ju = tid & 7;               // 0..7

    const uint32_t sW_base = smem_u32(sWu);
    const uint32_t sH_base = smem_u32(sHu);

    // ---- load W_hh rows (24 real + 8 zero pad) as fp16 into sWu ----
    for (int idx = tid; idx < 32 * 128; idx += 512) {
        const int rr = idx >> 7;
        const int cu = idx & 127;
        uint32_t val = 0u;
        if (rr < 24) {
            const int gate = rr >> 3;
            const int j    = jb + (rr & 7);
            const float2 w2 = *(const float2*)(W + (gate * GH + j) * GH + cu * 2);
            __half2 h2 = __floats2half2_rn(w2.x, w2.y);
            val = *(uint32_t*)&h2;
        }
        sWu[rr * SKW + cu] = val;
    }

    const int len = seglen[b];
    const float br_ = bh[0*GH + jb + ju];
    const float bz_ = bh[1*GH + jb + ju];
    const float bn_ = bh[2*GH + jb + ju];

    __syncthreads();

    // ---- preload W b-fragments ----
    uint32_t bfr[16][2];
    {
        const uint32_t b_loff = ((nt * 8 + (lane & 7)) * SKW + ((lane >> 3) & 3) * 4) * 4;
        #pragma unroll
        for (int kp = 0; kp < 8; kp++) {
            uint32_t r0, r1, r2, r3;
            LDSM4(r0, r1, r2, r3, sW_base + b_loff + kp * 64);
            bfr[2*kp][0] = r0; bfr[2*kp][1] = r1;
            bfr[2*kp+1][0] = r2; bfr[2*kp+1][1] = r3;
        }
    }

    const uint32_t a_loff = ((lane & 15) * SKW + (lane >> 4) * 4) * 4;

    float hprev = 0.0f;
    unsigned target = 0;

    for (int t = 0; t < TT; t++) {
        const int p = t & 1;
        const __half* hp = g_Hh + ((dir * 2 + p) * BB) * GH;
        __half* hn = g_Hh + ((dir * 2 + (p ^ 1)) * BB) * GH;

        const bool valid = (t < len);
        const int te = dir ? (len - 1 - t) : t;
        const long grow = (long)(b * TT + (valid ? te : 0)) * 1536 + dir * G3 + jb + ju;
        const float xr = G[grow];
        const float xz = G[grow + GH];
        const float xn = G[grow + 2 * GH];

        // fill sHu from global fp16 h (parity p)
        #pragma unroll
        for (int i = 0; i < 4; i++) {
            const int idx = tid + i * 512;
            const uint4 v = __ldcg(((const uint4*)hp) + idx);
            const int row = idx >> 5;
            const int ch  = idx & 31;
            *(uint4*)&sHu[row * SKW + ch * 4] = v;
        }
        __syncthreads();

        // mma: D[64x32] = H[64x256] @ W^T
        float dacc[4] = {0.f, 0.f, 0.f, 0.f};
        {
            const uint32_t abase = sH_base + a_loff + (mt * 16 * SKW) * 4;
            #pragma unroll
            for (int kt = 0; kt < 16; kt++) {
                uint32_t aa[4];
                LDSM4(aa[0], aa[1], aa[2], aa[3], abase + kt * 32);
                mma_f16(dacc, aa, bfr[kt]);
            }
        }
        {
            const int r0 = mt * 16 + gid;
            const int c0 = nt * 8 + 2 * tig;
            *(float2*)&sD[r0 * 36 + c0]       = make_float2(dacc[0], dacc[1]);
            *(float2*)&sD[(r0 + 8) * 36 + c0] = make_float2(dacc[2], dacc[3]);
        }
        __syncthreads();

        // elementwise GRU update
        const float pr = sD[b * 36 + ju]      + br_;
        const float pz = sD[b * 36 + 8 + ju]  + bz_;
        const float pn = sD[b * 36 + 16 + ju] + bn_;
        const float r = sigmoidf_(xr + pr);
        const float z = sigmoidf_(xz + pz);
        const float n = tanhf(xn + r * pn);
        const float hnew = valid ? ((1.0f - z) * n + z * hprev) : hprev;
        hprev = hnew;

        {
            __half hh = __float2half_rn(hnew);
            unsigned short us = *(unsigned short*)&hh;
            asm volatile("st.global.cg.u16 [%0], %1;"
                         :: "l"(hn + b * GH + jb + ju), "h"(us) : "memory");
        }
        if (valid)
            out[(long)(b * TT + te) * 512 + dir * GH + jb + ju] = hnew;
        else
            out[(long)(b * TT + t) * 512 + dir * GH + jb + ju] = 0.0f;

        // per-direction grid barrier: 32 arrivals; release/acquire ordering
        target += 32;
        __syncthreads();
        if (tid == 0) {
            asm volatile("red.add.release.gpu.global.u32 [%0], 1;"
                         :: "l"(bar) : "memory");
            unsigned v;
            do {
                asm volatile("ld.acquire.gpu.global.u32 %0, [%1];"
                             : "=r"(v) : "l"(bar) : "memory");
            } while (v < target);
        }
        __syncthreads();
    }
}

// ---------------------------------------------------------------------------
extern "C" void kernel_launch(void* const* d_in, const int* in_sizes, int n_in,
                              void* d_out, int out_size) {
    const float* seg   = (const float*)d_in[0];
    const int*   slen  = (const int*)  d_in[1];
    const float* Wq    = (const float*)d_in[2];
    const float* bq    = (const float*)d_in[3];
    const float* Wk    = (const float*)d_in[4];
    const float* bk    = (const float*)d_in[5];
    const float* Wv    = (const float*)d_in[6];
    const float* bv    = (const float*)d_in[7];
    const float* Wo    = (const float*)d_in[8];
    const float* bo    = (const float*)d_in[9];
    const float* Wihf  = (const float*)d_in[10];
    const float* Whhf  = (const float*)d_in[11];
    const float* bihf  = (const float*)d_in[12];
    const float* bhhf  = (const float*)d_in[13];
    const float* Wihb  = (const float*)d_in[14];
    const float* Whhb  = (const float*)d_in[15];
    const float* bihb  = (const float*)d_in[16];
    const float* bhhb  = (const float*)d_in[17];
    float* out = (float*)d_out;

    __half *pAh, *pAOh, *pWh, *pQKVh;
    float *pXf, *pG, *pBias;
    cudaGetSymbolAddress((void**)&pAh,   g_Ah);
    cudaGetSymbolAddress((void**)&pAOh,  g_AOh);
    cudaGetSymbolAddress((void**)&pXf,   g_Xf);
    cudaGetSymbolAddress((void**)&pQKVh, g_QKVh);
    cudaGetSymbolAddress((void**)&pG,    g_G);
    cudaGetSymbolAddress((void**)&pWh,   g_Wh);
    cudaGetSymbolAddress((void**)&pBias, g_bias);

    cudaFuncSetAttribute(mma_gemm, cudaFuncAttributeMaxDynamicSharedMemorySize, GEMM_SMEM);
    cudaFuncSetAttribute(gru_kernel, cudaFuncAttributeMaxDynamicSharedMemorySize, GRU_SMEM);

    // ---- prep (3 launches) ----
    prep_weights<<<512, 256>>>(Wq, Wk, Wv, Wo, Wihf, Wihb);
    prep_small<<<16, 256>>>(bq, bk, bv, bo, bihf, bihb);
    to_half<<<512, 256>>>(seg, pAh, (MROWS * DD) / 4);

    const dim3 blk(256);
    const dim3 gQKV(3072 / 256, MROWS / 128);
    const dim3 gO  (1024 / 256, MROWS / 128);
    const dim3 gG_ (1536 / 256, MROWS / 128);
    const int attnBlocks = BB * HH * 4;   // (b, h, s-tile)

    // layer 0
    mma_gemm<<<gQKV, blk, GEMM_SMEM>>>(pAh,  pWh + W_QKV0, pBias + B_QKV0, nullptr, nullptr, pQKVh, 3072);
    attn_kernel<<<attnBlocks, blk>>>(pQKVh, pAOh);
    mma_gemm<<<gO,   blk, GEMM_SMEM>>>(pAOh, pWh + W_O0,   pBias + B_O0,   seg,     pXf,  pAh,    1024);
    // layer 1
    mma_gemm<<<gQKV, blk, GEMM_SMEM>>>(pAh,  pWh + W_QKV1, pBias + B_QKV1, nullptr, nullptr, pQKVh, 3072);
    attn_kernel<<<attnBlocks, blk>>>(pQKVh, pAOh);
    mma_gemm<<<gO,   blk, GEMM_SMEM>>>(pAOh, pWh + W_O1,   pBias + B_O1,   pXf,     nullptr, pAh,  1024);
    // GRU input projections (fused fwd|bwd)
    mma_gemm<<<gG_,  blk, GEMM_SMEM>>>(pAh,  pWh + W_GRU,  pBias + B_GRU,  nullptr, pG,   nullptr, 1536);

    // BiGRU recurrence (tensor-core, persistent)
    gru_kernel<<<64, 512, GRU_SMEM>>>(pG, Whhf, Whhb, bhhf, bhhb, slen, out);
}

// round 16
// speedup vs baseline: 1.2595x; 1.2595x over previous
#include <cuda_runtime.h>
#include <cuda_fp16.h>
#include <math.h>
#include <stdint.h>

#define BB 64
#define TT 256
#define DD 1024
#define HH 8
#define GH 256
#define G3 768
#define MROWS (BB*TT)   // 16384

// ---------------- scratch (device globals; allocation forbidden) -----------
__device__ __align__(16) __half g_Ah [MROWS*DD];   // fp16 A mirror (seg_h / X_h)
__device__ __align__(16) __half g_AOh[MROWS*DD];   // fp16 attention output
__device__ __align__(16) float  g_Xf [MROWS*DD];   // fp32 X after layer0
__device__ __align__(16) __half g_QKVh[MROWS*3072];// fused QKV output (fp16)
__device__ __align__(16) float  g_G  [MROWS*1536]; // fused GRU gx (fwd|bwd), fp32
__device__ __align__(16) __half g_Wh [9961472];    // fp16 concat weights
__device__ __align__(16) float  g_bias[9728];      // concat biases (fp32)
__device__ __align__(16) __half g_Hh [2*2*BB*GH];  // fp16 h exchange [dir][parity][b][GH]
__device__ __align__(128) unsigned g_bar2[64];     // [0]: fwd counter, [32]: bwd counter

// Weight region offsets (elements)
#define W_QKV0 0
#define W_O0   3145728
#define W_QKV1 4194304
#define W_O1   7340032
#define W_GRU  8388608
// Bias offsets
#define B_QKV0 0
#define B_O0   3072
#define B_QKV1 4096
#define B_O1   7168
#define B_GRU  8192

// ---------------------------------------------------------------------------
__device__ __forceinline__ uint32_t smem_u32(const void* p) {
    uint32_t a;
    asm("{ .reg .u64 t; cvta.to.shared.u64 t, %1; cvt.u32.u64 %0, t; }" : "=r"(a) : "l"(p));
    return a;
}
__device__ __forceinline__ void cp_async16(uint32_t dst_smem, const void* src) {
    asm volatile("cp.async.cg.shared.global [%0], [%1], 16;" :: "r"(dst_smem), "l"(src));
}
#define CP_COMMIT() asm volatile("cp.async.commit_group;" ::: "memory")
#define CP_WAIT1()  asm volatile("cp.async.wait_group 1;" ::: "memory")
#define CP_WAIT0()  asm volatile("cp.async.wait_group 0;" ::: "memory")

#define LDSM4(r0, r1, r2, r3, addr) \
    asm volatile("ldmatrix.sync.aligned.m8n8.x4.shared.b16 {%0,%1,%2,%3}, [%4];" \
        : "=r"(r0), "=r"(r1), "=r"(r2), "=r"(r3) : "r"(addr))

__device__ __forceinline__ void mma_f16(float* d, const uint32_t* a, const uint32_t* b) {
    asm volatile(
        "mma.sync.aligned.m16n8k16.row.col.f32.f16.f16.f32 "
        "{%0,%1,%2,%3}, {%4,%5,%6,%7}, {%8,%9}, {%0,%1,%2,%3};"
        : "+f"(d[0]), "+f"(d[1]), "+f"(d[2]), "+f"(d[3])
        : "r"(a[0]), "r"(a[1]), "r"(a[2]), "r"(a[3]), "r"(b[0]), "r"(b[1]));
}

__device__ __forceinline__ float4 ld_h4(const __half* p) {
    const uint2 u = *(const uint2*)p;
    const __half2* h = (const __half2*)&u;
    const float2 f01 = __half22float2(h[0]);
    const float2 f23 = __half22float2(h[1]);
    return make_float4(f01.x, f01.y, f23.x, f23.y);
}

// ---------------------------------------------------------------------------
// prep: all 10 weight matrices -> fp16 concat (dst is contiguous flat index)
// ---------------------------------------------------------------------------
__global__ void prep_weights(const float* __restrict__ Wq, const float* __restrict__ Wk,
                             const float* __restrict__ Wv, const float* __restrict__ Wo,
                             const float* __restrict__ Wihf, const float* __restrict__ Wihb) {
    const int MW4 = 262144;   // 1M floats / 4
    const int GW4 = 196608;   // 768K floats / 4
    const long total = 8L * MW4 + 2L * GW4;   // 2490368 float4s
    const float* srcs[10] = {Wq, Wk, Wv, Wo,
                             Wq + 1048576, Wk + 1048576, Wv + 1048576, Wo + 1048576,
                             Wihf, Wihb};
    const long stride = (long)gridDim.x * blockDim.x;
    for (long idx = (long)blockIdx.x * blockDim.x + threadIdx.x; idx < total; idx += stride) {
        int r; long off;
        if (idx < 8L * MW4) { r = (int)(idx >> 18); off = idx & (MW4 - 1); }
        else {
            long k = idx - 8L * MW4;
            r = 8 + (int)(k >= GW4);
            off = k - (long)(r - 8) * GW4;
        }
        const float4 v = ((const float4*)srcs[r])[off];
        __half2 h01 = __floats2half2_rn(v.x, v.y);
        __half2 h23 = __floats2half2_rn(v.z, v.w);
        uint2 u;
        u.x = *(uint32_t*)&h01;
        u.y = *(uint32_t*)&h23;
        ((uint2*)g_Wh)[idx] = u;
    }
}

// ---------------------------------------------------------------------------
// prep: concat biases + zero h parity-0 + zero barrier counters
// ---------------------------------------------------------------------------
__global__ void prep_small(const float* __restrict__ bq, const float* __restrict__ bk,
                           const float* __restrict__ bv, const float* __restrict__ bo,
                           const float* __restrict__ bihf, const float* __restrict__ bihb) {
    const float* bsrc[8] = {bq, bk, bv, bo, bq + 1024, bk + 1024, bv + 1024, bo + 1024};
    const int stride = gridDim.x * blockDim.x;
    for (int idx = blockIdx.x * blockDim.x + threadIdx.x; idx < 16384; idx += stride) {
        if (idx < 9728) {
            float val;
            if (idx < 8192)       val = bsrc[idx >> 10][idx & 1023];
            else if (idx < 8960)  val = bihf[idx - 8192];
            else                  val = bihb[idx - 8960];
            g_bias[idx] = val;
        }
        if (idx < BB*GH/2) {
            ((uint32_t*)g_Hh)[idx] = 0u;                 // dir0 parity0
            ((uint32_t*)(g_Hh + 2*BB*GH))[idx] = 0u;     // dir1 parity0
        }
        if (idx < 64) g_bar2[idx] = 0u;
    }
}

__global__ void to_half(const float* __restrict__ src, __half* __restrict__ dst, int n4) {
    int i = blockIdx.x * blockDim.x + threadIdx.x;
    int stride = gridDim.x * blockDim.x;
    for (int k = i; k < n4; k += stride) {
        float4 v = ((const float4*)src)[k];
        __half2 h01 = __floats2half2_rn(v.x, v.y);
        __half2 h23 = __floats2half2_rn(v.z, v.w);
        uint2 u;
        u.x = *(uint32_t*)&h01;
        u.y = *(uint32_t*)&h23;
        ((uint2*)dst)[k] = u;
    }
}

// ---------------------------------------------------------------------------
// fp16 mma GEMM with ldmatrix fragments: C = A[M,1024] @ W[Nc,1024]^T + bias
// BM=128, BN=128, BK=32, 8 warps (2x4), warp tile 64x32, 3-stage cp.async
// (R12 configuration — measured local optimum for this legacy-HMMA path)
// ---------------------------------------------------------------------------
#define SKH 20                          // b32 units per smem row (80B, 16B-mult)
#define STG_U32 (128*SKH)
#define GEMM_SMEM (3 * 2 * STG_U32 * 4) // 61440 bytes

__global__ __launch_bounds__(256, 2)
void mma_gemm(const __half* __restrict__ A, const __half* __restrict__ Wp,
              const float* __restrict__ bias, const float* __restrict__ res,
              float* __restrict__ Cf, __half* __restrict__ Ch, int Nc) {
    extern __shared__ uint32_t smu[];
    const uint32_t sbase = smem_u32(smu);
    const int tid  = threadIdx.x;
    const int wid  = tid >> 5;
    const int lane = tid & 31;
    const int warp_m = wid & 1;
    const int warp_n = wid >> 1;
    const int gid = lane >> 2;
    const int tig = lane & 3;
    const int bm = blockIdx.y * 128;
    const int bn = blockIdx.x * 128;

    const int ldr = tid >> 1;
    const int ldc = (tid & 1) << 1;

    auto load_stage = [&](int kt, int p) {
        const uint32_t sA = sbase + p * 2 * STG_U32 * 4;
        const uint32_t sB = sA + STG_U32 * 4;
        const __half* ga = A  + (long)(bm + ldr) * DD + kt * 32;
        const __half* gb = Wp + (long)(bn + ldr) * DD + kt * 32;
        #pragma unroll
        for (int c = 0; c < 2; c++) {
            const int ch = ldc + c;
            cp_async16(sA + (ldr * SKH + ch * 4) * 4, ga + ch * 8);
            cp_async16(sB + (ldr * SKH + ch * 4) * 4, gb + ch * 8);
        }
    };

    float acc[4][4][4];
    #pragma unroll
    for (int mt = 0; mt < 4; mt++)
        #pragma unroll
        for (int nt = 0; nt < 4; nt++)
            #pragma unroll
            for (int q = 0; q < 4; q++) acc[mt][nt][q] = 0.0f;

    const uint32_t a_loff = ((lane & 15) * SKH + (lane >> 4) * 4) * 4;
    const uint32_t b_loff = (((lane & 7) + (lane >> 4) * 8) * SKH + ((lane >> 3) & 1) * 4) * 4;

    const int NK = DD / 32;   // 32
    load_stage(0, 0); CP_COMMIT();
    load_stage(1, 1); CP_COMMIT();

    for (int kt = 0; kt < NK; kt++) {
        CP_WAIT1();
        __syncthreads();
        if (kt + 2 < NK) load_stage(kt + 2, (kt + 2) % 3);
        CP_COMMIT();

        const uint32_t sAb = sbase + (kt % 3) * 2 * STG_U32 * 4;
        const uint32_t sBb = sAb + STG_U32 * 4;
        const int mb = warp_m * 64;
        const int nb = warp_n * 32;
        #pragma unroll
        for (int ks = 0; ks < 2; ks++) {
            uint32_t afr[4][4], bfr[4][2];
            #pragma unroll
            for (int mt = 0; mt < 4; mt++) {
                const uint32_t ad = sAb + a_loff + ((mb + mt * 16) * SKH + ks * 8) * 4;
                LDSM4(afr[mt][0], afr[mt][1], afr[mt][2], afr[mt][3], ad);
            }
            #pragma unroll
            for (int np = 0; np < 2; np++) {
                const uint32_t bd = sBb + b_loff + ((nb + np * 16) * SKH + ks * 8) * 4;
                LDSM4(bfr[2*np][0], bfr[2*np][1], bfr[2*np+1][0], bfr[2*np+1][1], bd);
            }
            #pragma unroll
            for (int mt = 0; mt < 4; mt++)
                #pragma unroll
                for (int nt = 0; nt < 4; nt++)
                    mma_f16(acc[mt][nt], afr[mt], bfr[nt]);
        }
        // buffer reuse ordered by the next iteration's post-wait barrier.
    }

    // epilogue
    #pragma unroll
    for (int mt = 0; mt < 4; mt++) {
        #pragma unroll
        for (int nt = 0; nt < 4; nt++) {
            const long row0 = bm + warp_m * 64 + mt * 16 + gid;
            const int  colg = bn + warp_n * 32 + nt * 8 + 2 * tig;
            #pragma unroll
            for (int hf = 0; hf < 2; hf++) {
                const long row = row0 + hf * 8;
                float2 v;
                v.x = acc[mt][nt][hf * 2 + 0];
                v.y = acc[mt][nt][hf * 2 + 1];
                const float2 bv = *(const float2*)(bias + colg);
                v.x += bv.x; v.y += bv.y;
                if (res) {
                    const float2 rv = *(const float2*)(res + row * Nc + colg);
                    v.x += rv.x; v.y += rv.y;
                }
                if (Cf) *(float2*)(Cf + row * Nc + colg) = v;
                if (Ch) {
                    __half2 hv = __floats2half2_rn(v.x, v.y);
                    *(__half2*)(Ch + row * Nc + colg) = hv;
                }
            }
        }
    }
}

// ---------------------------------------------------------------------------
// Tiled banded attention: block = (b, h, s-tile of 64). K/V band rows staged
// in smem via cp.async (<=70 rows x 256B each). 8 warps, 8 s per warp.
// ---------------------------------------------------------------------------
__global__ __launch_bounds__(256)
void attn_kernel(const __half* __restrict__ QKV, __half* __restrict__ Oh) {
    __shared__ __half Ks[70][128];
    __shared__ __half Vs[70][128];

    const int tid = threadIdx.x;
    const int st = blockIdx.x & 3;
    const int h  = (blockIdx.x >> 2) & 7;
    const int b  = blockIdx.x >> 5;
    const int s0 = st * 64;
    const int tlo = max(s0 - 3, 0);
    const int thi = min(s0 + 66, TT - 1);
    const int nrow = thi - tlo + 1;   // <= 70

    const long base = (long)(b * TT + tlo) * 3072 + h * 128;
    for (int idx = tid; idx < nrow * 16; idx += 256) {
        const int r = idx >> 4;
        const int c = idx & 15;
        cp_async16(smem_u32(&Ks[r][c * 8]), QKV + base + (long)r * 3072 + 1024 + c * 8);
        cp_async16(smem_u32(&Vs[r][c * 8]), QKV + base + (long)r * 3072 + 2048 + c * 8);
    }
    CP_COMMIT();
    CP_WAIT0();
    __syncthreads();

    const int wrp  = tid >> 5;
    const int lane = tid & 31;

    for (int i = 0; i < 8; i++) {
        const int s = s0 + wrp * 8 + i;
        const float4 q4 = ld_h4(QKV + (long)(b * TT + s) * 3072 + h * 128 + lane * 4);

        float sc[7];
        float m = -1e30f;
        #pragma unroll
        for (int j = 0; j < 7; j++) {
            const int t = s - 3 + j;
            const bool vld = (t >= 0) && (t < TT);
            const int ti = (vld ? t : (t < 0 ? 0 : TT - 1)) - tlo;
            const float4 k4 = ld_h4(&Ks[ti][lane * 4]);
            float p = q4.x*k4.x + q4.y*k4.y + q4.z*k4.z + q4.w*k4.w;
            p += __shfl_xor_sync(0xffffffffu, p, 16);
            p += __shfl_xor_sync(0xffffffffu, p, 8);
            p += __shfl_xor_sync(0xffffffffu, p, 4);
            p += __shfl_xor_sync(0xffffffffu, p, 2);
            p += __shfl_xor_sync(0xffffffffu, p, 1);
            p = vld ? (p * 0.088388347648318447f) : -1e30f;
            sc[j] = p;
            m = fmaxf(m, p);
        }
        float sum = 0.0f;
        #pragma unroll
        for (int j = 0; j < 7; j++) {
            const float e = __expf(sc[j] - m);
            sc[j] = e;
            sum += e;
        }
        const float inv = 1.0f / sum;
        float4 o = make_float4(0.f, 0.f, 0.f, 0.f);
        #pragma unroll
        for (int j = 0; j < 7; j++) {
            const int t = s - 3 + j;
            const int ti = ((t >= 0) ? ((t < TT) ? t : TT - 1) : 0) - tlo;
            const float w = sc[j] * inv;
            const float4 v4 = ld_h4(&Vs[ti][lane * 4]);
            o.x += w * v4.x; o.y += w * v4.y; o.z += w * v4.z; o.w += w * v4.w;
        }
        __half2 h01 = __floats2half2_rn(o.x, o.y);
        __half2 h23 = __floats2half2_rn(o.z, o.w);
        uint2 u;
        u.x = *(uint32_t*)&h01;
        u.y = *(uint32_t*)&h23;
        *(uint2*)(Oh + (long)(b * TT + s) * 1024 + h * 128 + lane * 4) = u;
    }
}

// ---------------------------------------------------------------------------
// BiGRU recurrence on tensor cores. 64 blocks x 512 thr (32 blocks/dir,
// 8 hidden units each). W_hh as persistent register b-fragments; h exchanged
// fp16 via L2; fp32 h carry thread-local. Per-direction counter barrier;
// out-store and next-step gx prefetch overlapped with the barrier poll.
// ---------------------------------------------------------------------------
#define SKW 132   // u32 per smem row (256 halves + pad; 528B, 16B-mult)
#define GRU_SMEM ((32*SKW + 64*SKW) * 4 + 64*36*4)   // 59904 B

__device__ __forceinline__ float sigmoidf_(float x) { return 1.0f / (1.0f + expf(-x)); }

__global__ __launch_bounds__(512, 1)
void gru_kernel(const float* __restrict__ G,
                const float* __restrict__ Whhf, const float* __restrict__ Whhb,
                const float* __restrict__ bhhf, const float* __restrict__ bhhb,
                const int* __restrict__ seglen, float* __restrict__ out) {
    extern __shared__ uint32_t dsm[];
    uint32_t* sWu = dsm;                 // [32][SKW]
    uint32_t* sHu = dsm + 32 * SKW;      // [64][SKW]
    float*    sD  = (float*)(dsm + 96 * SKW);  // [64][36]

    const int tid = threadIdx.x;
    const int dir = blockIdx.x >> 5;
    const int jb  = (blockIdx.x & 31) * 8;
    const float* W  = dir ? Whhb : Whhf;
    const float* bh = dir ? bhhb : bhhf;
    unsigned* bar = g_bar2 + dir * 32;   // per-direction counter (128B apart)

    const int lane = tid & 31;
    const int wrp  = tid >> 5;            // 0..15
    const int mt   = wrp & 3;
    const int nt   = wrp >> 2;            // 0..3
    const int gid  = lane >> 2;
    const int tig  = lane & 3;

    const int b  = tid >> 3;              // 0..63
    const int ju = tid & 7;               // 0..7

    const uint32_t sW_base = smem_u32(sWu);
    const uint32_t sH_base = smem_u32(sHu);

    // ---- load W_hh rows (24 real + 8 zero pad) as fp16 into sWu ----
    for (int idx = tid; idx < 32 * 128; idx += 512) {
        const int rr = idx >> 7;
        const int cu = idx & 127;
        uint32_t val = 0u;
        if (rr < 24) {
            const int gate = rr >> 3;
            const int j    = jb + (rr & 7);
            const float2 w2 = *(const float2*)(W + (gate * GH + j) * GH + cu * 2);
            __half2 h2 = __floats2half2_rn(w2.x, w2.y);
            val = *(uint32_t*)&h2;
        }
        sWu[rr * SKW + cu] = val;
    }

    const int len = seglen[b];
    const float br_ = bh[0*GH + jb + ju];
    const float bz_ = bh[1*GH + jb + ju];
    const float bn_ = bh[2*GH + jb + ju];

    __syncthreads();

    // ---- preload W b-fragments ----
    uint32_t bfr[16][2];
    {
        const uint32_t b_loff = ((nt * 8 + (lane & 7)) * SKW + ((lane >> 3) & 3) * 4) * 4;
        #pragma unroll
        for (int kp = 0; kp < 8; kp++) {
            uint32_t r0, r1, r2, r3;
            LDSM4(r0, r1, r2, r3, sW_base + b_loff + kp * 64);
            bfr[2*kp][0] = r0; bfr[2*kp][1] = r1;
            bfr[2*kp+1][0] = r2; bfr[2*kp+1][1] = r3;
        }
    }

    const uint32_t a_loff = ((lane & 15) * SKW + (lane >> 4) * 4) * 4;

    float hprev = 0.0f;
    unsigned target = 0;

    // gx prefetch state for step 0
    bool valid = (0 < len);
    int  te_cur = dir ? (len - 1) : 0;
    {
        const long grow0 = (long)(b * TT + (valid ? te_cur : 0)) * 1536 + dir * G3 + jb + ju;
        // initial loads (not overlapped; one-time cost)
        hprev = 0.0f;
    }
    long grow = (long)(b * TT + (valid ? te_cur : 0)) * 1536 + dir * G3 + jb + ju;
    float xr = G[grow];
    float xz = G[grow + GH];
    float xn = G[grow + 2 * GH];

    for (int t = 0; t < TT; t++) {
        const int p = t & 1;
        const __half* hp = g_Hh + ((dir * 2 + p) * BB) * GH;
        __half* hn = g_Hh + ((dir * 2 + (p ^ 1)) * BB) * GH;

        // fill sHu from global fp16 h (parity p)
        #pragma unroll
        for (int i = 0; i < 4; i++) {
            const int idx = tid + i * 512;
            const uint4 v = __ldcg(((const uint4*)hp) + idx);
            const int row = idx >> 5;
            const int ch  = idx & 31;
            *(uint4*)&sHu[row * SKW + ch * 4] = v;
        }
        __syncthreads();

        // mma: D[64x32] = H[64x256] @ W^T
        float dacc[4] = {0.f, 0.f, 0.f, 0.f};
        {
            const uint32_t abase = sH_base + a_loff + (mt * 16 * SKW) * 4;
            #pragma unroll
            for (int kt = 0; kt < 16; kt++) {
                uint32_t aa[4];
                LDSM4(aa[0], aa[1], aa[2], aa[3], abase + kt * 32);
                mma_f16(dacc, aa, bfr[kt]);
            }
        }
        {
            const int r0 = mt * 16 + gid;
            const int c0 = nt * 8 + 2 * tig;
            *(float2*)&sD[r0 * 36 + c0]       = make_float2(dacc[0], dacc[1]);
            *(float2*)&sD[(r0 + 8) * 36 + c0] = make_float2(dacc[2], dacc[3]);
        }
        __syncthreads();

        // elementwise GRU update (gx preloaded last iteration)
        const float pr = sD[b * 36 + ju]      + br_;
        const float pz = sD[b * 36 + 8 + ju]  + bz_;
        const float pn = sD[b * 36 + 16 + ju] + bn_;
        const float r = sigmoidf_(xr + pr);
        const float z = sigmoidf_(xz + pz);
        const float n = tanhf(xn + r * pn);
        const float hnew = valid ? ((1.0f - z) * n + z * hprev) : hprev;

        // h store for next step (must precede barrier arrival)
        {
            __half hh = __float2half_rn(hnew);
            unsigned short us = *(unsigned short*)&hh;
            asm volatile("st.global.cg.u16 [%0], %1;"
                         :: "l"(hn + b * GH + jb + ju), "h"(us) : "memory");
        }

        // compute next-step gx coordinates
        const int tn = t + 1;
        const bool validn = (tn < len);
        const int ten = dir ? (len - 1 - tn) : tn;
        const long grown = (long)(b * TT + (validn ? ten : 0)) * 1536 + dir * G3 + jb + ju;

        if (t < TT - 1) {
            // barrier arrival (h stores ordered via syncthreads + release-red)
            target += 32;
            __syncthreads();
            if (tid == 0) {
                asm volatile("red.add.release.gpu.global.u32 [%0], 1;"
                             :: "l"(bar) : "memory");
            }
            // overlap with poll: out store + next gx prefetch
            if (valid)
                out[(long)(b * TT + te_cur) * 512 + dir * GH + jb + ju] = hnew;
            else
                out[(long)(b * TT + t) * 512 + dir * GH + jb + ju] = 0.0f;
            const float xrn = G[grown];
            const float xzn = G[grown + GH];
            const float xnn = G[grown + 2 * GH];
            if (tid == 0) {
                unsigned v;
                do {
                    asm volatile("ld.acquire.gpu.global.u32 %0, [%1];"
                                 : "=r"(v) : "l"(bar) : "memory");
                } while (v < target);
            }
            __syncthreads();
            xr = xrn; xz = xzn; xn = xnn;
        } else {
            // final step: no barrier needed
            if (valid)
                out[(long)(b * TT + te_cur) * 512 + dir * GH + jb + ju] = hnew;
            else
                out[(long)(b * TT + t) * 512 + dir * GH + jb + ju] = 0.0f;
        }

        hprev = hnew;
        valid = validn;
        te_cur = ten;
    }
}

// ---------------------------------------------------------------------------
extern "C" void kernel_launch(void* const* d_in, const int* in_sizes, int n_in,
                              void* d_out, int out_size) {
    const float* seg   = (const float*)d_in[0];
    const int*   slen  = (const int*)  d_in[1];
    const float* Wq    = (const float*)d_in[2];
    const float* bq    = (const float*)d_in[3];
    const float* Wk    = (const float*)d_in[4];
    const float* bk    = (const float*)d_in[5];
    const float* Wv    = (const float*)d_in[6];
    const float* bv    = (const float*)d_in[7];
    const float* Wo    = (const float*)d_in[8];
    const float* bo    = (const float*)d_in[9];
    const float* Wihf  = (const float*)d_in[10];
    const float* Whhf  = (const float*)d_in[11];
    const float* bihf  = (const float*)d_in[12];
    const float* bhhf  = (const float*)d_in[13];
    const float* Wihb  = (const float*)d_in[14];
    const float* Whhb  = (const float*)d_in[15];
    const float* bihb  = (const float*)d_in[16];
    const float* bhhb  = (const float*)d_in[17];
    float* out = (float*)d_out;

    __half *pAh, *pAOh, *pWh, *pQKVh;
    float *pXf, *pG, *pBias;
    cudaGetSymbolAddress((void**)&pAh,   g_Ah);
    cudaGetSymbolAddress((void**)&pAOh,  g_AOh);
    cudaGetSymbolAddress((void**)&pXf,   g_Xf);
    cudaGetSymbolAddress((void**)&pQKVh, g_QKVh);
    cudaGetSymbolAddress((void**)&pG,    g_G);
    cudaGetSymbolAddress((void**)&pWh,   g_Wh);
    cudaGetSymbolAddress((void**)&pBias, g_bias);

    cudaFuncSetAttribute(mma_gemm, cudaFuncAttributeMaxDynamicSharedMemorySize, GEMM_SMEM);
    cudaFuncSetAttribute(gru_kernel, cudaFuncAttributeMaxDynamicSharedMemorySize, GRU_SMEM);

    // ---- prep (3 launches) ----
    prep_weights<<<512, 256>>>(Wq, Wk, Wv, Wo, Wihf, Wihb);
    prep_small<<<16, 256>>>(bq, bk, bv, bo, bihf, bihb);
    to_half<<<512, 256>>>(seg, pAh, (MROWS * DD) / 4);

    const dim3 blk(256);
    const dim3 gQKV(3072 / 128, MROWS / 128);
    const dim3 gO  (1024 / 128, MROWS / 128);
    const dim3 gG_ (1536 / 128, MROWS / 128);
    const int attnBlocks = BB * HH * 4;   // (b, h, s-tile)

    // layer 0
    mma_gemm<<<gQKV, blk, GEMM_SMEM>>>(pAh,  pWh + W_QKV0, pBias + B_QKV0, nullptr, nullptr, pQKVh, 3072);
    attn_kernel<<<attnBlocks, blk>>>(pQKVh, pAOh);
    mma_gemm<<<gO,   blk, GEMM_SMEM>>>(pAOh, pWh + W_O0,   pBias + B_O0,   seg,     pXf,  pAh,    1024);
    // layer 1
    mma_gemm<<<gQKV, blk, GEMM_SMEM>>>(pAh,  pWh + W_QKV1, pBias + B_QKV1, nullptr, nullptr, pQKVh, 3072);
    attn_kernel<<<attnBlocks, blk>>>(pQKVh, pAOh);
    mma_gemm<<<gO,   blk, GEMM_SMEM>>>(pAOh, pWh + W_O1,   pBias + B_O1,   pXf,     nullptr, pAh,  1024);
    // GRU input projections (fused fwd|bwd)
    mma_gemm<<<gG_,  blk, GEMM_SMEM>>>(pAh,  pWh + W_GRU,  pBias + B_GRU,  nullptr, pG,   nullptr, 1536);

    // BiGRU recurrence (tensor-core, persistent)
    gru_kernel<<<64, 512, GRU_SMEM>>>(pG, Whhf, Whhb, bhhf, bhhb, slen, out);
}

// round 17
// speedup vs baseline: 1.2639x; 1.0035x over previous
#include <cuda_runtime.h>
#include <cuda_fp16.h>
#include <math.h>
#include <stdint.h>

#define BB 64
#define TT 256
#define DD 1024
#define HH 8
#define GH 256
#define G3 768
#define MROWS (BB*TT)   // 16384

// ---------------- scratch (device globals; allocation forbidden) -----------
__device__ __align__(16) __half g_Ah [MROWS*DD];   // fp16 A mirror (seg_h / X_h)
__device__ __align__(16) __half g_AOh[MROWS*DD];   // fp16 attention output
__device__ __align__(16) float  g_Xf [MROWS*DD];   // fp32 X after layer0
__device__ __align__(16) __half g_QKVh[MROWS*3072];// fused QKV output (fp16)
__device__ __align__(16) float  g_G  [MROWS*1536]; // fused GRU gx (fwd|bwd), fp32
__device__ __align__(16) __half g_Wh [9961472];    // fp16 concat weights
__device__ __align__(16) float  g_bias[9728];      // concat biases (fp32)
__device__ __align__(16) __half g_Hh [2*2*BB*GH];  // fp16 h exchange [dir][parity][b][GH]
__device__ __align__(128) unsigned g_bar2[64];     // [0]: fwd counter, [32]: bwd counter

// Weight region offsets (elements)
#define W_QKV0 0
#define W_O0   3145728
#define W_QKV1 4194304
#define W_O1   7340032
#define W_GRU  8388608
// Bias offsets
#define B_QKV0 0
#define B_O0   3072
#define B_QKV1 4096
#define B_O1   7168
#define B_GRU  8192

// ---------------------------------------------------------------------------
__device__ __forceinline__ uint32_t smem_u32(const void* p) {
    uint32_t a;
    asm("{ .reg .u64 t; cvta.to.shared.u64 t, %1; cvt.u32.u64 %0, t; }" : "=r"(a) : "l"(p));
    return a;
}
__device__ __forceinline__ void cp_async16(uint32_t dst_smem, const void* src) {
    asm volatile("cp.async.cg.shared.global [%0], [%1], 16;" :: "r"(dst_smem), "l"(src));
}
#define CP_COMMIT() asm volatile("cp.async.commit_group;" ::: "memory")
#define CP_WAIT1()  asm volatile("cp.async.wait_group 1;" ::: "memory")
#define CP_WAIT0()  asm volatile("cp.async.wait_group 0;" ::: "memory")

#define LDSM4(r0, r1, r2, r3, addr) \
    asm volatile("ldmatrix.sync.aligned.m8n8.x4.shared.b16 {%0,%1,%2,%3}, [%4];" \
        : "=r"(r0), "=r"(r1), "=r"(r2), "=r"(r3) : "r"(addr))

__device__ __forceinline__ void mma_f16(float* d, const uint32_t* a, const uint32_t* b) {
    asm volatile(
        "mma.sync.aligned.m16n8k16.row.col.f32.f16.f16.f32 "
        "{%0,%1,%2,%3}, {%4,%5,%6,%7}, {%8,%9}, {%0,%1,%2,%3};"
        : "+f"(d[0]), "+f"(d[1]), "+f"(d[2]), "+f"(d[3])
        : "r"(a[0]), "r"(a[1]), "r"(a[2]), "r"(a[3]), "r"(b[0]), "r"(b[1]));
}

__device__ __forceinline__ float4 ld_h4(const __half* p) {
    const uint2 u = *(const uint2*)p;
    const __half2* h = (const __half2*)&u;
    const float2 f01 = __half22float2(h[0]);
    const float2 f23 = __half22float2(h[1]);
    return make_float4(f01.x, f01.y, f23.x, f23.y);
}

// ---------------------------------------------------------------------------
// prep: all 10 weight matrices -> fp16 concat (dst is contiguous flat index)
// ---------------------------------------------------------------------------
__global__ void prep_weights(const float* __restrict__ Wq, const float* __restrict__ Wk,
                             const float* __restrict__ Wv, const float* __restrict__ Wo,
                             const float* __restrict__ Wihf, const float* __restrict__ Wihb) {
    const int MW4 = 262144;   // 1M floats / 4
    const int GW4 = 196608;   // 768K floats / 4
    const long total = 8L * MW4 + 2L * GW4;   // 2490368 float4s
    const float* srcs[10] = {Wq, Wk, Wv, Wo,
                             Wq + 1048576, Wk + 1048576, Wv + 1048576, Wo + 1048576,
                             Wihf, Wihb};
    const long stride = (long)gridDim.x * blockDim.x;
    for (long idx = (long)blockIdx.x * blockDim.x + threadIdx.x; idx < total; idx += stride) {
        int r; long off;
        if (idx < 8L * MW4) { r = (int)(idx >> 18); off = idx & (MW4 - 1); }
        else {
            long k = idx - 8L * MW4;
            r = 8 + (int)(k >= GW4);
            off = k - (long)(r - 8) * GW4;
        }
        const float4 v = ((const float4*)srcs[r])[off];
        __half2 h01 = __floats2half2_rn(v.x, v.y);
        __half2 h23 = __floats2half2_rn(v.z, v.w);
        uint2 u;
        u.x = *(uint32_t*)&h01;
        u.y = *(uint32_t*)&h23;
        ((uint2*)g_Wh)[idx] = u;
    }
}

// ---------------------------------------------------------------------------
// prep: concat biases + zero h parity-0 + zero barrier counters
// ---------------------------------------------------------------------------
__global__ void prep_small(const float* __restrict__ bq, const float* __restrict__ bk,
                           const float* __restrict__ bv, const float* __restrict__ bo,
                           const float* __restrict__ bihf, const float* __restrict__ bihb) {
    const float* bsrc[8] = {bq, bk, bv, bo, bq + 1024, bk + 1024, bv + 1024, bo + 1024};
    const int stride = gridDim.x * blockDim.x;
    for (int idx = blockIdx.x * blockDim.x + threadIdx.x; idx < 16384; idx += stride) {
        if (idx < 9728) {
            float val;
            if (idx < 8192)       val = bsrc[idx >> 10][idx & 1023];
            else if (idx < 8960)  val = bihf[idx - 8192];
            else                  val = bihb[idx - 8960];
            g_bias[idx] = val;
        }
        if (idx < BB*GH/2) {
            ((uint32_t*)g_Hh)[idx] = 0u;                 // dir0 parity0
            ((uint32_t*)(g_Hh + 2*BB*GH))[idx] = 0u;     // dir1 parity0
        }
        if (idx < 64) g_bar2[idx] = 0u;
    }
}

__global__ void to_half(const float* __restrict__ src, __half* __restrict__ dst, int n4) {
    int i = blockIdx.x * blockDim.x + threadIdx.x;
    int stride = gridDim.x * blockDim.x;
    for (int k = i; k < n4; k += stride) {
        float4 v = ((const float4*)src)[k];
        __half2 h01 = __floats2half2_rn(v.x, v.y);
        __half2 h23 = __floats2half2_rn(v.z, v.w);
        uint2 u;
        u.x = *(uint32_t*)&h01;
        u.y = *(uint32_t*)&h23;
        ((uint2*)dst)[k] = u;
    }
}

// ---------------------------------------------------------------------------
// fp16 mma GEMM with ldmatrix fragments: C = A[M,1024] @ W[Nc,1024]^T + bias
// BM=128, BN=128, BK=32, 8 warps (2x4), warp tile 64x32, 3-stage cp.async
// (R12 configuration — measured local optimum for this legacy-HMMA path)
// ---------------------------------------------------------------------------
#define SKH 20                          // b32 units per smem row (80B, 16B-mult)
#define STG_U32 (128*SKH)
#define GEMM_SMEM (3 * 2 * STG_U32 * 4) // 61440 bytes

__global__ __launch_bounds__(256, 2)
void mma_gemm(const __half* __restrict__ A, const __half* __restrict__ Wp,
              const float* __restrict__ bias, const float* __restrict__ res,
              float* __restrict__ Cf, __half* __restrict__ Ch, int Nc) {
    extern __shared__ uint32_t smu[];
    const uint32_t sbase = smem_u32(smu);
    const int tid  = threadIdx.x;
    const int wid  = tid >> 5;
    const int lane = tid & 31;
    const int warp_m = wid & 1;
    const int warp_n = wid >> 1;
    const int gid = lane >> 2;
    const int tig = lane & 3;
    const int bm = blockIdx.y * 128;
    const int bn = blockIdx.x * 128;

    const int ldr = tid >> 1;
    const int ldc = (tid & 1) << 1;

    auto load_stage = [&](int kt, int p) {
        const uint32_t sA = sbase + p * 2 * STG_U32 * 4;
        const uint32_t sB = sA + STG_U32 * 4;
        const __half* ga = A  + (long)(bm + ldr) * DD + kt * 32;
        const __half* gb = Wp + (long)(bn + ldr) * DD + kt * 32;
        #pragma unroll
        for (int c = 0; c < 2; c++) {
            const int ch = ldc + c;
            cp_async16(sA + (ldr * SKH + ch * 4) * 4, ga + ch * 8);
            cp_async16(sB + (ldr * SKH + ch * 4) * 4, gb + ch * 8);
        }
    };

    float acc[4][4][4];
    #pragma unroll
    for (int mt = 0; mt < 4; mt++)
        #pragma unroll
        for (int nt = 0; nt < 4; nt++)
            #pragma unroll
            for (int q = 0; q < 4; q++) acc[mt][nt][q] = 0.0f;

    const uint32_t a_loff = ((lane & 15) * SKH + (lane >> 4) * 4) * 4;
    const uint32_t b_loff = (((lane & 7) + (lane >> 4) * 8) * SKH + ((lane >> 3) & 1) * 4) * 4;

    const int NK = DD / 32;   // 32
    load_stage(0, 0); CP_COMMIT();
    load_stage(1, 1); CP_COMMIT();

    for (int kt = 0; kt < NK; kt++) {
        CP_WAIT1();
        __syncthreads();
        if (kt + 2 < NK) load_stage(kt + 2, (kt + 2) % 3);
        CP_COMMIT();

        const uint32_t sAb = sbase + (kt % 3) * 2 * STG_U32 * 4;
        const uint32_t sBb = sAb + STG_U32 * 4;
        const int mb = warp_m * 64;
        const int nb = warp_n * 32;
        #pragma unroll
        for (int ks = 0; ks < 2; ks++) {
            uint32_t afr[4][4], bfr[4][2];
            #pragma unroll
            for (int mt = 0; mt < 4; mt++) {
                const uint32_t ad = sAb + a_loff + ((mb + mt * 16) * SKH + ks * 8) * 4;
                LDSM4(afr[mt][0], afr[mt][1], afr[mt][2], afr[mt][3], ad);
            }
            #pragma unroll
            for (int np = 0; np < 2; np++) {
                const uint32_t bd = sBb + b_loff + ((nb + np * 16) * SKH + ks * 8) * 4;
                LDSM4(bfr[2*np][0], bfr[2*np][1], bfr[2*np+1][0], bfr[2*np+1][1], bd);
            }
            #pragma unroll
            for (int mt = 0; mt < 4; mt++)
                #pragma unroll
                for (int nt = 0; nt < 4; nt++)
                    mma_f16(acc[mt][nt], afr[mt], bfr[nt]);
        }
        // buffer reuse ordered by the next iteration's post-wait barrier.
    }

    // epilogue
    #pragma unroll
    for (int mt = 0; mt < 4; mt++) {
        #pragma unroll
        for (int nt = 0; nt < 4; nt++) {
            const long row0 = bm + warp_m * 64 + mt * 16 + gid;
            const int  colg = bn + warp_n * 32 + nt * 8 + 2 * tig;
            #pragma unroll
            for (int hf = 0; hf < 2; hf++) {
                const long row = row0 + hf * 8;
                float2 v;
                v.x = acc[mt][nt][hf * 2 + 0];
                v.y = acc[mt][nt][hf * 2 + 1];
                const float2 bv = *(const float2*)(bias + colg);
                v.x += bv.x; v.y += bv.y;
                if (res) {
                    const float2 rv = *(const float2*)(res + row * Nc + colg);
                    v.x += rv.x; v.y += rv.y;
                }
                if (Cf) *(float2*)(Cf + row * Nc + colg) = v;
                if (Ch) {
                    __half2 hv = __floats2half2_rn(v.x, v.y);
                    *(__half2*)(Ch + row * Nc + colg) = hv;
                }
            }
        }
    }
}

// ---------------------------------------------------------------------------
// Tiled banded attention: block = (b, h, s-tile of 64). K/V band rows staged
// in smem via cp.async (<=70 rows x 256B each). 8 warps, 8 s per warp.
// ---------------------------------------------------------------------------
__global__ __launch_bounds__(256)
void attn_kernel(const __half* __restrict__ QKV, __half* __restrict__ Oh) {
    __shared__ __half Ks[70][128];
    __shared__ __half Vs[70][128];

    const int tid = threadIdx.x;
    const int st = blockIdx.x & 3;
    const int h  = (blockIdx.x >> 2) & 7;
    const int b  = blockIdx.x >> 5;
    const int s0 = st * 64;
    const int tlo = max(s0 - 3, 0);
    const int thi = min(s0 + 66, TT - 1);
    const int nrow = thi - tlo + 1;   // <= 70

    const long base = (long)(b * TT + tlo) * 3072 + h * 128;
    for (int idx = tid; idx < nrow * 16; idx += 256) {
        const int r = idx >> 4;
        const int c = idx & 15;
        cp_async16(smem_u32(&Ks[r][c * 8]), QKV + base + (long)r * 3072 + 1024 + c * 8);
        cp_async16(smem_u32(&Vs[r][c * 8]), QKV + base + (long)r * 3072 + 2048 + c * 8);
    }
    CP_COMMIT();
    CP_WAIT0();
    __syncthreads();

    const int wrp  = tid >> 5;
    const int lane = tid & 31;

    for (int i = 0; i < 8; i++) {
        const int s = s0 + wrp * 8 + i;
        const float4 q4 = ld_h4(QKV + (long)(b * TT + s) * 3072 + h * 128 + lane * 4);

        float sc[7];
        float m = -1e30f;
        #pragma unroll
        for (int j = 0; j < 7; j++) {
            const int t = s - 3 + j;
            const bool vld = (t >= 0) && (t < TT);
            const int ti = (vld ? t : (t < 0 ? 0 : TT - 1)) - tlo;
            const float4 k4 = ld_h4(&Ks[ti][lane * 4]);
            float p = q4.x*k4.x + q4.y*k4.y + q4.z*k4.z + q4.w*k4.w;
            p += __shfl_xor_sync(0xffffffffu, p, 16);
            p += __shfl_xor_sync(0xffffffffu, p, 8);
            p += __shfl_xor_sync(0xffffffffu, p, 4);
            p += __shfl_xor_sync(0xffffffffu, p, 2);
            p += __shfl_xor_sync(0xffffffffu, p, 1);
            p = vld ? (p * 0.088388347648318447f) : -1e30f;
            sc[j] = p;
            m = fmaxf(m, p);
        }
        float sum = 0.0f;
        #pragma unroll
        for (int j = 0; j < 7; j++) {
            const float e = __expf(sc[j] - m);
            sc[j] = e;
            sum += e;
        }
        const float inv = 1.0f / sum;
        float4 o = make_float4(0.f, 0.f, 0.f, 0.f);
        #pragma unroll
        for (int j = 0; j < 7; j++) {
            const int t = s - 3 + j;
            const int ti = ((t >= 0) ? ((t < TT) ? t : TT - 1) : 0) - tlo;
            const float w = sc[j] * inv;
            const float4 v4 = ld_h4(&Vs[ti][lane * 4]);
            o.x += w * v4.x; o.y += w * v4.y; o.z += w * v4.z; o.w += w * v4.w;
        }
        __half2 h01 = __floats2half2_rn(o.x, o.y);
        __half2 h23 = __floats2half2_rn(o.z, o.w);
        uint2 u;
        u.x = *(uint32_t*)&h01;
        u.y = *(uint32_t*)&h23;
        *(uint2*)(Oh + (long)(b * TT + s) * 1024 + h * 128 + lane * 4) = u;
    }
}

// ---------------------------------------------------------------------------
// BiGRU recurrence on tensor cores. 64 blocks x 512 thr (32 blocks/dir,
// 8 hidden units each). W_hh as persistent register b-fragments; h exchanged
// fp16 via L2; fp32 h carry thread-local. Per-direction counter barrier;
// MMA chain split into two independent accumulators (halved HMMA latency).
// ---------------------------------------------------------------------------
#define SKW 132   // u32 per smem row (256 halves + pad; 528B, 16B-mult)
#define GRU_SMEM ((32*SKW + 64*SKW) * 4 + 64*36*4)   // 59904 B

__device__ __forceinline__ float sigmoidf_(float x) { return 1.0f / (1.0f + expf(-x)); }

__global__ __launch_bounds__(512, 1)
void gru_kernel(const float* __restrict__ G,
                const float* __restrict__ Whhf, const float* __restrict__ Whhb,
                const float* __restrict__ bhhf, const float* __restrict__ bhhb,
                const int* __restrict__ seglen, float* __restrict__ out) {
    extern __shared__ uint32_t dsm[];
    uint32_t* sWu = dsm;                 // [32][SKW]
    uint32_t* sHu = dsm + 32 * SKW;      // [64][SKW]
    float*    sD  = (float*)(dsm + 96 * SKW);  // [64][36]

    const int tid = threadIdx.x;
    const int dir = blockIdx.x >> 5;
    const int jb  = (blockIdx.x & 31) * 8;
    const float* W  = dir ? Whhb : Whhf;
    const float* bh = dir ? bhhb : bhhf;
    unsigned* bar = g_bar2 + dir * 32;   // per-direction counter (128B apart)

    const int lane = tid & 31;
    const int wrp  = tid >> 5;            // 0..15
    const int mt   = wrp & 3;
    const int nt   = wrp >> 2;            // 0..3
    const int gid  = lane >> 2;
    const int tig  = lane & 3;

    const int b  = tid >> 3;              // 0..63
    const int ju = tid & 7;               // 0..7

    const uint32_t sW_base = smem_u32(sWu);
    const uint32_t sH_base = smem_u32(sHu);

    // ---- load W_hh rows (24 real + 8 zero pad) as fp16 into sWu ----
    for (int idx = tid; idx < 32 * 128; idx += 512) {
        const int rr = idx >> 7;
        const int cu = idx & 127;
        uint32_t val = 0u;
        if (rr < 24) {
            const int gate = rr >> 3;
            const int j    = jb + (rr & 7);
            const float2 w2 = *(const float2*)(W + (gate * GH + j) * GH + cu * 2);
            __half2 h2 = __floats2half2_rn(w2.x, w2.y);
            val = *(uint32_t*)&h2;
        }
        sWu[rr * SKW + cu] = val;
    }

    const int len = seglen[b];
    const float br_ = bh[0*GH + jb + ju];
    const float bz_ = bh[1*GH + jb + ju];
    const float bn_ = bh[2*GH + jb + ju];

    __syncthreads();

    // ---- preload W b-fragments ----
    uint32_t bfr[16][2];
    {
        const uint32_t b_loff = ((nt * 8 + (lane & 7)) * SKW + ((lane >> 3) & 3) * 4) * 4;
        #pragma unroll
        for (int kp = 0; kp < 8; kp++) {
            uint32_t r0, r1, r2, r3;
            LDSM4(r0, r1, r2, r3, sW_base + b_loff + kp * 64);
            bfr[2*kp][0] = r0; bfr[2*kp][1] = r1;
            bfr[2*kp+1][0] = r2; bfr[2*kp+1][1] = r3;
        }
    }

    const uint32_t a_loff = ((lane & 15) * SKW + (lane >> 4) * 4) * 4;

    float hprev = 0.0f;
    unsigned target = 0;

    bool valid = (0 < len);
    int  te_cur = dir ? (len - 1) : 0;
    long grow = (long)(b * TT + (valid ? te_cur : 0)) * 1536 + dir * G3 + jb + ju;
    float xr = G[grow];
    float xz = G[grow + GH];
    float xn = G[grow + 2 * GH];

    for (int t = 0; t < TT; t++) {
        const int p = t & 1;
        const __half* hp = g_Hh + ((dir * 2 + p) * BB) * GH;
        __half* hn = g_Hh + ((dir * 2 + (p ^ 1)) * BB) * GH;

        // fill sHu from global fp16 h (parity p)
        #pragma unroll
        for (int i = 0; i < 4; i++) {
            const int idx = tid + i * 512;
            const uint4 v = __ldcg(((const uint4*)hp) + idx);
            const int row = idx >> 5;
            const int ch  = idx & 31;
            *(uint4*)&sHu[row * SKW + ch * 4] = v;
        }
        __syncthreads();

        // mma: D[64x32] = H[64x256] @ W^T — two independent accumulator chains
        float dacc0[4] = {0.f, 0.f, 0.f, 0.f};
        float dacc1[4] = {0.f, 0.f, 0.f, 0.f};
        {
            const uint32_t abase = sH_base + a_loff + (mt * 16 * SKW) * 4;
            #pragma unroll
            for (int kt = 0; kt < 16; kt += 2) {
                uint32_t aa0[4], aa1[4];
                LDSM4(aa0[0], aa0[1], aa0[2], aa0[3], abase + kt * 32);
                LDSM4(aa1[0], aa1[1], aa1[2], aa1[3], abase + (kt + 1) * 32);
                mma_f16(dacc0, aa0, bfr[kt]);
                mma_f16(dacc1, aa1, bfr[kt + 1]);
            }
        }
        {
            const int r0 = mt * 16 + gid;
            const int c0 = nt * 8 + 2 * tig;
            *(float2*)&sD[r0 * 36 + c0] =
                make_float2(dacc0[0] + dacc1[0], dacc0[1] + dacc1[1]);
            *(float2*)&sD[(r0 + 8) * 36 + c0] =
                make_float2(dacc0[2] + dacc1[2], dacc0[3] + dacc1[3]);
        }
        __syncthreads();

        // elementwise GRU update (gx preloaded last iteration)
        const float pr = sD[b * 36 + ju]      + br_;
        const float pz = sD[b * 36 + 8 + ju]  + bz_;
        const float pn = sD[b * 36 + 16 + ju] + bn_;
        const float r = sigmoidf_(xr + pr);
        const float z = sigmoidf_(xz + pz);
        const float n = tanhf(xn + r * pn);
        const float hnew = valid ? ((1.0f - z) * n + z * hprev) : hprev;

        // h store for next step (must precede barrier arrival)
        {
            __half hh = __float2half_rn(hnew);
            unsigned short us = *(unsigned short*)&hh;
            asm volatile("st.global.cg.u16 [%0], %1;"
                         :: "l"(hn + b * GH + jb + ju), "h"(us) : "memory");
        }

        const int tn = t + 1;
        const bool validn = (tn < len);
        const int ten = dir ? (len - 1 - tn) : tn;
        const long grown = (long)(b * TT + (validn ? ten : 0)) * 1536 + dir * G3 + jb + ju;

        if (t < TT - 1) {
            target += 32;
            __syncthreads();
            if (tid == 0) {
                asm volatile("red.add.release.gpu.global.u32 [%0], 1;"
                             :: "l"(bar) : "memory");
            }
            // overlap with poll: out store + next gx prefetch
            if (valid)
                out[(long)(b * TT + te_cur) * 512 + dir * GH + jb + ju] = hnew;
            else
                out[(long)(b * TT + t) * 512 + dir * GH + jb + ju] = 0.0f;
            const float xrn = G[grown];
            const float xzn = G[grown + GH];
            const float xnn = G[grown + 2 * GH];
            if (tid == 0) {
                unsigned v;
                do {
                    asm volatile("ld.acquire.gpu.global.u32 %0, [%1];"
                                 : "=r"(v) : "l"(bar) : "memory");
                } while (v < target);
            }
            __syncthreads();
            xr = xrn; xz = xzn; xn = xnn;
        } else {
            if (valid)
                out[(long)(b * TT + te_cur) * 512 + dir * GH + jb + ju] = hnew;
            else
                out[(long)(b * TT + t) * 512 + dir * GH + jb + ju] = 0.0f;
        }

        hprev = hnew;
        valid = validn;
        te_cur = ten;
    }
}

// ---------------------------------------------------------------------------
extern "C" void kernel_launch(void* const* d_in, const int* in_sizes, int n_in,
                              void* d_out, int out_size) {
    const float* seg   = (const float*)d_in[0];
    const int*   slen  = (const int*)  d_in[1];
    const float* Wq    = (const float*)d_in[2];
    const float* bq    = (const float*)d_in[3];
    const float* Wk    = (const float*)d_in[4];
    const float* bk    = (const float*)d_in[5];
    const float* Wv    = (const float*)d_in[6];
    const float* bv    = (const float*)d_in[7];
    const float* Wo    = (const float*)d_in[8];
    const float* bo    = (const float*)d_in[9];
    const float* Wihf  = (const float*)d_in[10];
    const float* Whhf  = (const float*)d_in[11];
    const float* bihf  = (const float*)d_in[12];
    const float* bhhf  = (const float*)d_in[13];
    const float* Wihb  = (const float*)d_in[14];
    const float* Whhb  = (const float*)d_in[15];
    const float* bihb  = (const float*)d_in[16];
    const float* bhhb  = (const float*)d_in[17];
    float* out = (float*)d_out;

    __half *pAh, *pAOh, *pWh, *pQKVh;
    float *pXf, *pG, *pBias;
    cudaGetSymbolAddress((void**)&pAh,   g_Ah);
    cudaGetSymbolAddress((void**)&pAOh,  g_AOh);
    cudaGetSymbolAddress((void**)&pXf,   g_Xf);
    cudaGetSymbolAddress((void**)&pQKVh, g_QKVh);
    cudaGetSymbolAddress((void**)&pG,    g_G);
    cudaGetSymbolAddress((void**)&pWh,   g_Wh);
    cudaGetSymbolAddress((void**)&pBias, g_bias);

    cudaFuncSetAttribute(mma_gemm, cudaFuncAttributeMaxDynamicSharedMemorySize, GEMM_SMEM);
    cudaFuncSetAttribute(gru_kernel, cudaFuncAttributeMaxDynamicSharedMemorySize, GRU_SMEM);

    // ---- prep (3 launches) ----
    prep_weights<<<512, 256>>>(Wq, Wk, Wv, Wo, Wihf, Wihb);
    prep_small<<<16, 256>>>(bq, bk, bv, bo, bihf, bihb);
    to_half<<<512, 256>>>(seg, pAh, (MROWS * DD) / 4);

    const dim3 blk(256);
    const dim3 gQKV(3072 / 128, MROWS / 128);
    const dim3 gO  (1024 / 128, MROWS / 128);
    const dim3 gG_ (1536 / 128, MROWS / 128);
    const int attnBlocks = BB * HH * 4;   // (b, h, s-tile)

    // layer 0
    mma_gemm<<<gQKV, blk, GEMM_SMEM>>>(pAh,  pWh + W_QKV0, pBias + B_QKV0, nullptr, nullptr, pQKVh, 3072);
    attn_kernel<<<attnBlocks, blk>>>(pQKVh, pAOh);
    mma_gemm<<<gO,   blk, GEMM_SMEM>>>(pAOh, pWh + W_O0,   pBias + B_O0,   seg,     pXf,  pAh,    1024);
    // layer 1
    mma_gemm<<<gQKV, blk, GEMM_SMEM>>>(pAh,  pWh + W_QKV1, pBias + B_QKV1, nullptr, nullptr, pQKVh, 3072);
    attn_kernel<<<attnBlocks, blk>>>(pQKVh, pAOh);
    mma_gemm<<<gO,   blk, GEMM_SMEM>>>(pAOh, pWh + W_O1,   pBias + B_O1,   pXf,     nullptr, pAh,  1024);
    // GRU input projections (fused fwd|bwd)
    mma_gemm<<<gG_,  blk, GEMM_SMEM>>>(pAh,  pWh + W_GRU,  pBias + B_GRU,  nullptr, pG,   nullptr, 1536);

    // BiGRU recurrence (tensor-core, persistent)
    gru_kernel<<<64, 512, GRU_SMEM>>>(pG, Whhf, Whhb, bhhf, bhhb, slen, out);
}